// round 11
// baseline (speedup 1.0000x reference)
#include <cuda_runtime.h>
#include <math.h>

// MaskAlignmentLoss: fused kernel, wide 1024-thread blocks to shorten the
// per-block latency critical path.
// Pixel blocks (16): one 32x32 tile each; single-pass cap-5 binning in smem,
//   exact ring search (RB=3) + overflow list + brute-force guard.
// Vert blocks (27): mask bitset via ballot + exact per-row scan.
// B=4, N=6890, H=W=64. Pixel units; scale 1/64 per term.

#define BATCH   4
#define NV      6890
#define HW      4096
#define INF2    1.0e18f
#define INV64   0.015625f
#define BIGF    1.0e9f
#define NT      1024
#define NB_PIX  16                  // 4 tiles x 4 batches (32x32 tiles)
#define NB_VERT 27                  // 27648 >= 27560 verts
#define NBLK    (NB_PIX + NB_VERT)  // 43
#define RB      3                   // ring margin (px)
#define REG     38                  // region width = 32 + 2*RB
#define NBIN    (REG * REG)         // 1444
#define CAP     5                   // slots per bin
#define OVF_CAP 64
#define SMEM_BYTES (NBIN * 4 + NBIN * CAP * 8 + OVF_CAP * 8)   // 64048

// -------- persistent device state (monotonic; no init across replays) --------
__device__ float    g_partial[NBLK];
__device__ unsigned g_ticket;

__device__ __forceinline__ float sqrt_ap(float x) {
    float r; asm("sqrt.approx.f32 %0, %1;" : "=f"(r) : "f"(x)); return r;
}

extern __shared__ __align__(16) unsigned dyn_u[];

__global__ void __launch_bounds__(NT) k_fused(const float* __restrict__ vert,
                                              const int*   __restrict__ mask,
                                              float*       __restrict__ out) {
    __shared__ float red[NT];
    __shared__ unsigned s_ovf_cnt;
    __shared__ int s_fallback;
    __shared__ int lastflag;

    const int bx = blockIdx.x, tid = threadIdx.x;
    const int lane = tid & 31, wid = tid >> 5;
    float s = 0.0f;

    if (bx < NB_PIX) {
        // ========== pixel -> nearest vert, one 32x32 tile per block ==========
        const int b  = bx >> 2;
        const int t  = bx & 3;
        const int ox = (t & 1) * 32, oy = (t >> 1) * 32;   // tile origin
        const int rx0 = ox - RB, ry0 = oy - RB;            // region origin
        const int cx = ox + (tid & 31), cy = oy + (tid >> 5);

        unsigned* scnt = dyn_u;                                    // [NBIN]
        float2*   sbin = (float2*)(dyn_u + NBIN);                  // [NBIN*CAP]
        float2*   sovf = (float2*)(dyn_u + NBIN + NBIN * CAP * 2); // [OVF_CAP]

        // early independent load (overlaps with binning latency)
        const int mymask = mask[b * HW + cy * 64 + cx];

        // zero bin counts (1444 over 1024 threads)
        scnt[tid] = 0;
        if (tid < NBIN - NT) scnt[tid + NT] = 0;
        if (tid == 0) { s_ovf_cnt = 0; s_fallback = 0; }
        __syncthreads();

        // single-pass binning: float4 loads (2 verts each), direct append.
        // ceil(3445/1024) = 4 iterations.
        const float2* vb  = (const float2*)(vert + (size_t)b * NV * 2);
        const float4* vb4 = (const float4*)vb;
        for (int i = tid; i < NV / 2; i += NT) {
            float4 q = vb4[i];
#pragma unroll
            for (int h = 0; h < 2; h++) {
                float vx = h ? q.z : q.x, vy = h ? q.w : q.y;
                int lx = min(63, (int)vx) - rx0;
                int ly = min(63, (int)vy) - ry0;
                if ((unsigned)lx < REG && (unsigned)ly < REG) {
                    int bin = ly * REG + lx;
                    unsigned slot = atomicAdd(&scnt[bin], 1u);
                    if (slot < CAP) {
                        sbin[bin * CAP + slot] = make_float2(vx, vy);
                    } else {
                        unsigned o = atomicAdd(&s_ovf_cnt, 1u);
                        if (o < OVF_CAP) sovf[o] = make_float2(vx, vy);
                        else s_fallback = 1;
                    }
                }
            }
        }
        __syncthreads();

        if (mymask > 0) {
            const float px = (float)cx, py = (float)cy;
            float best = INF2;
#define EVAL_VBIN(X, Y) do {                                               \
            int bin = ((Y) - ry0) * REG + ((X) - rx0);                     \
            int n = min(scnt[bin], (unsigned)CAP);                         \
            for (int k = 0; k < n; k++) {                                  \
                float2 w = sbin[bin * CAP + k];                            \
                float dx = px - w.x, dy = py - w.y;                        \
                best = fminf(best, fmaf(dx, dx, dy * dy));                 \
            } } while (0)
            for (int r = 0; r <= RB; r++) {
                if (r > 0 && best <= (float)((r - 1) * (r - 1))) break;
                int x0 = max(cx - r, 0), x1 = min(cx + r, 63);
                int yt = cy - r;
                if (yt >= 0) for (int x = x0; x <= x1; x++) EVAL_VBIN(x, yt);
                if (r > 0) {
                    int yb = cy + r;
                    if (yb <= 63) for (int x = x0; x <= x1; x++) EVAL_VBIN(x, yb);
                    int yy0 = max(cy - r + 1, 0), yy1 = min(cy + r - 1, 63);
                    int xl = cx - r, xr = cx + r;
                    if (xl >= 0)  for (int y = yy0; y <= yy1; y++) EVAL_VBIN(xl, y);
                    if (xr <= 63) for (int y = yy0; y <= yy1; y++) EVAL_VBIN(xr, y);
                }
            }
            // unconditional overflow scan (real verts -> cannot underestimate)
            int no = min(s_ovf_cnt, (unsigned)OVF_CAP);
            for (int k = 0; k < no; k++) {
                float2 w = sovf[k];
                float dx = px - w.x, dy = py - w.y;
                best = fminf(best, fmaf(dx, dx, dy * dy));
            }
            // exactness guards: region miss (best > RB^2) or list overflow
            if (s_fallback || !(best <= (float)(RB * RB))) {
                for (int i = 0; i < NV; i++) {
                    float2 w = vb[i];
                    float dx = px - w.x, dy = py - w.y;
                    best = fminf(best, fmaf(dx, dx, dy * dy));
                }
            }
            s = sqrt_ap(best) * INV64;
        }
    } else {
        // ================== vert -> nearest valid pixel ==================
        const int g0 = (bx - NB_PIX) * NT;
        const int b_lo = g0 / NV;
        const int b_hi = min((g0 + NT - 1) / NV, BATCH - 1);
        unsigned* sb = dyn_u;    // up to 2*128 bitset words

        for (int bi = 0; bi <= b_hi - b_lo; bi++) {
            const int* mbase = mask + (b_lo + bi) * HW;
            // 128 words over 32 warps: 4 ballots per warp
#pragma unroll
            for (int it = 0; it < 4; it++) {
                int wl = it * 32 + wid;
                int val = mbase[wl * 32 + lane] > 0;
                unsigned word = __ballot_sync(0xffffffffu, val);
                if (lane == 0) sb[bi * 128 + wl] = word;
            }
        }
        __syncthreads();

        const int g = g0 + tid;
        if (g < BATCH * NV) {
            const int b = g / NV;
            float2 v = ((const float2*)vert)[g];
            const float vx = v.x, vy = v.y;
            const int xc = min(63, (int)vx), cy = min(63, (int)vy);
            const unsigned* mb = &sb[(b - b_lo) * 128];
            const unsigned long long lmask =
                (xc >= 63) ? ~0ull : ((1ull << (xc + 1)) - 1ull);
            float best = INF2;

            // exact per-row minimum via two monotone candidate sets:
            //  highest set bit <= xc, lowest set bit >= xc+1
#define ROW_EVAL(Y, DY) do {                                                     \
            unsigned long long m = (unsigned long long)mb[2 * (Y)] |             \
                                   ((unsigned long long)mb[2 * (Y) + 1] << 32);  \
            if (m) {                                                             \
                float dy2 = (DY) * (DY);                                         \
                unsigned long long ml = m & lmask;                               \
                if (ml) {                                                        \
                    float dx = vx - (float)(63 - __clzll((long long)ml));        \
                    best = fminf(best, fmaf(dx, dx, dy2));                       \
                }                                                                \
                unsigned long long mr = (m >> xc) >> 1;                          \
                if (mr) {                                                        \
                    float dx = (float)(xc + __ffsll((long long)mr)) - vx;        \
                    best = fminf(best, fmaf(dx, dx, dy2));                       \
                }                                                                \
            } } while (0)

            for (int d = 0; d < 64; d++) {
                if (d > 0 && best <= (float)((d - 1) * (d - 1))) break;
                int yd = cy + d;
                if (yd < 64) { float dy = vy - (float)yd; if (dy * dy < best) ROW_EVAL(yd, dy); }
                if (d > 0) {
                    int yu = cy - d;
                    if (yu >= 0) { float dy = vy - (float)yu; if (dy * dy < best) ROW_EVAL(yu, dy); }
                }
            }
            s = (best >= 1.0e17f) ? BIGF : sqrt_ap(best) * INV64;
        }
    }

    // ============ block reduce -> partial; last finisher sums all ============
    __syncthreads();
    red[tid] = s;
    __syncthreads();
#pragma unroll
    for (int d = NT / 2; d > 0; d >>= 1) {
        if (tid < d) red[tid] += red[tid + d];
        __syncthreads();
    }
    if (tid == 0) {
        g_partial[bx] = red[0];
        __threadfence();
        unsigned t = atomicAdd(&g_ticket, 1u);
        lastflag = ((t % (unsigned)NBLK) == (unsigned)(NBLK - 1));
    }
    __syncthreads();
    if (lastflag) {
        __threadfence();
        float v = (tid < NBLK) ? *(volatile float*)&g_partial[tid] : 0.0f;
        red[tid] = v;
        __syncthreads();
#pragma unroll
        for (int d = NT / 2; d > 0; d >>= 1) {
            if (tid < d) red[tid] += red[tid + d];
            __syncthreads();
        }
        if (tid == 0) out[0] = red[0];
    }
}

extern "C" void kernel_launch(void* const* d_in, const int* in_sizes, int n_in,
                              void* d_out, int out_size) {
    const float* vert2d = (const float*)d_in[0];   // [B, N, 2] float32 (pixel units)
    const int*   mask   = (const int*)d_in[1];     // [B, H, W] int32
    float* out = (float*)d_out;
    (void)in_sizes; (void)n_in; (void)out_size;

    static int configured = 0;
    if (!configured) {
        cudaFuncSetAttribute(k_fused, cudaFuncAttributeMaxDynamicSharedMemorySize, SMEM_BYTES);
        configured = 1;
    }
    k_fused<<<NBLK, NT, SMEM_BYTES>>>(vert2d, mask, out);
}

// round 12
// speedup vs baseline: 1.1382x; 1.1382x over previous
#include <cuda_runtime.h>
#include <math.h>

// MaskAlignmentLoss: fused kernel (R10 structure + latency-chain trims).
// Pixel blocks (64): 16x16 tile, single-pass cap-6 binning (prefetch-pipelined),
//   exact ring search (RB=4) + overflow list + brute-force guard.
// Vert blocks (108): mask bitset via ballot + exact per-row scan.
// B=4, N=6890, H=W=64. Pixel units; scale 1/64 per term.

#define BATCH   4
#define NV      6890
#define HW      4096
#define INF2    1.0e18f
#define INV64   0.015625f
#define BIGF    1.0e9f
#define NB_PIX  64                  // 16 tiles x 4 batches
#define NB_VERT 108                 // 27648 >= 27560 verts
#define NBLK    (NB_PIX + NB_VERT)  // 172
#define RB      4                   // ring margin (px)
#define REG     24                  // region width = 16 + 2*RB
#define NBIN    (REG * REG)         // 576
#define CAP     6                   // slots per bin
#define OVF_CAP 128
#define SMEM_BYTES (NBIN * 4 + NBIN * CAP * 8 + OVF_CAP * 8)   // 30976

// -------- persistent device state (monotonic; no init across replays) --------
__device__ float    g_partial[NBLK];
__device__ unsigned g_ticket;

__device__ __forceinline__ float sqrt_ap(float x) {
    float r; asm("sqrt.approx.f32 %0, %1;" : "=f"(r) : "f"(x)); return r;
}

extern __shared__ __align__(16) unsigned dyn_u[];

__global__ void __launch_bounds__(256) k_fused(const float* __restrict__ vert,
                                               const int*   __restrict__ mask,
                                               float*       __restrict__ out) {
    __shared__ float red[8];
    __shared__ unsigned s_ovf_cnt;
    __shared__ int s_fallback;
    __shared__ int lastflag;

    const int bx = blockIdx.x, tid = threadIdx.x;
    const int lane = tid & 31, wid = tid >> 5;
    float s = 0.0f;

    if (bx < NB_PIX) {
        // ============ pixel -> nearest vert, one 16x16 tile per block ============
        const int b  = bx >> 4;
        const int t  = bx & 15;
        const int ox = (t & 3) * 16, oy = (t >> 2) * 16;   // tile origin
        const int rx0 = ox - RB, ry0 = oy - RB;            // region origin
        const int cx = ox + (tid & 15), cy = oy + (tid >> 4);

        unsigned* scnt = dyn_u;                                    // [NBIN]
        float2*   sbin = (float2*)(dyn_u + NBIN);                  // [NBIN*CAP]
        float2*   sovf = (float2*)(dyn_u + NBIN + NBIN * CAP * 2); // [OVF_CAP]

        // early independent load (overlaps with binning latency)
        const int mymask = mask[b * HW + cy * 64 + cx];

        // zero bin counts (576 words over 256 threads)
        scnt[tid] = 0; scnt[tid + 256] = 0;
        if (tid < NBIN - 512) scnt[tid + 512] = 0;
        if (tid == 0) { s_ovf_cnt = 0; s_fallback = 0; }
        __syncthreads();

        // single-pass binning, prefetch-pipelined float4 loads (2 verts each)
        const float2* vb  = (const float2*)(vert + (size_t)b * NV * 2);
        const float4* vb4 = (const float4*)vb;               // NV even -> 3445
        {
            const int half = NV / 2;                          // 3445
            bool vnext = (tid < half);
            float4 qnext = vnext ? vb4[tid] : make_float4(0, 0, 0, 0);
            for (int k = 0; k * 256 < half; k++) {
                float4 q = qnext; bool v = vnext;
                int inx = tid + (k + 1) * 256;
                vnext = (inx < half);
                if (vnext) qnext = vb4[inx];                  // prefetch next iter
                if (v) {
#pragma unroll
                    for (int h = 0; h < 2; h++) {
                        float vx = h ? q.z : q.x, vy = h ? q.w : q.y;
                        int lx = min(63, (int)vx) - rx0;
                        int ly = min(63, (int)vy) - ry0;
                        if ((unsigned)lx < REG && (unsigned)ly < REG) {
                            int bin = ly * REG + lx;
                            unsigned slot = atomicAdd(&scnt[bin], 1u);
                            if (slot < CAP) {
                                sbin[bin * CAP + slot] = make_float2(vx, vy);
                            } else {
                                unsigned o = atomicAdd(&s_ovf_cnt, 1u);
                                if (o < OVF_CAP) sovf[o] = make_float2(vx, vy);
                                else s_fallback = 1;
                            }
                        }
                    }
                }
            }
        }
        __syncthreads();

        if (mymask > 0) {
            const float px = (float)cx, py = (float)cy;
            float best = INF2;
#define EVAL_VBIN(X, Y) do {                                               \
            int bin = ((Y) - ry0) * REG + ((X) - rx0);                     \
            int n = min(scnt[bin], (unsigned)CAP);                         \
            for (int k = 0; k < n; k++) {                                  \
                float2 w = sbin[bin * CAP + k];                            \
                float dx = px - w.x, dy = py - w.y;                        \
                best = fminf(best, fmaf(dx, dx, dy * dy));                 \
            } } while (0)
            for (int r = 0; r <= RB; r++) {
                if (r > 0 && best <= (float)((r - 1) * (r - 1))) break;
                int x0 = max(cx - r, 0), x1 = min(cx + r, 63);
                int yt = cy - r;
                if (yt >= 0) for (int x = x0; x <= x1; x++) EVAL_VBIN(x, yt);
                if (r > 0) {
                    int yb = cy + r;
                    if (yb <= 63) for (int x = x0; x <= x1; x++) EVAL_VBIN(x, yb);
                    int yy0 = max(cy - r + 1, 0), yy1 = min(cy + r - 1, 63);
                    int xl = cx - r, xr = cx + r;
                    if (xl >= 0)  for (int y = yy0; y <= yy1; y++) EVAL_VBIN(xl, y);
                    if (xr <= 63) for (int y = yy0; y <= yy1; y++) EVAL_VBIN(xr, y);
                }
            }
            // unconditional overflow scan (real verts -> cannot underestimate)
            int no = min(s_ovf_cnt, (unsigned)OVF_CAP);
            for (int k = 0; k < no; k++) {
                float2 w = sovf[k];
                float dx = px - w.x, dy = py - w.y;
                best = fminf(best, fmaf(dx, dx, dy * dy));
            }
            // exactness guards: region miss (best > RB^2) or list overflow
            if (s_fallback || !(best <= (float)(RB * RB))) {
                for (int i = 0; i < NV; i++) {
                    float2 w = vb[i];
                    float dx = px - w.x, dy = py - w.y;
                    best = fminf(best, fmaf(dx, dx, dy * dy));
                }
            }
            s = sqrt_ap(best) * INV64;
        }
    } else {
        // ================== vert -> nearest valid pixel ==================
        const int g0 = (bx - NB_PIX) * 256;
        const int b_lo = g0 / NV;
        const int b_hi = min((g0 + 255) / NV, BATCH - 1);
        unsigned* sb = dyn_u;    // up to 2*128 bitset words

        for (int bi = 0; bi <= b_hi - b_lo; bi++) {
            const int* mbase = mask + (b_lo + bi) * HW;
#pragma unroll
            for (int it = 0; it < 16; it++) {
                int wl = it * 8 + wid;                       // word 0..127
                int val = mbase[wl * 32 + lane] > 0;
                unsigned word = __ballot_sync(0xffffffffu, val);
                if (lane == 0) sb[bi * 128 + wl] = word;
            }
        }
        __syncthreads();

        const int g = g0 + tid;
        if (g < BATCH * NV) {
            const int b = g / NV;
            float2 v = ((const float2*)vert)[g];
            const float vx = v.x, vy = v.y;
            const int xc = min(63, (int)vx), cy = min(63, (int)vy);
            const unsigned* mb = &sb[(b - b_lo) * 128];
            const unsigned long long lmask =
                (xc >= 63) ? ~0ull : ((1ull << (xc + 1)) - 1ull);
            float best = INF2;

            // exact per-row minimum via two monotone candidate sets:
            //  highest set bit <= xc, lowest set bit >= xc+1
#define ROW_EVAL(Y, DY) do {                                                     \
            unsigned long long m = (unsigned long long)mb[2 * (Y)] |             \
                                   ((unsigned long long)mb[2 * (Y) + 1] << 32);  \
            if (m) {                                                             \
                float dy2 = (DY) * (DY);                                         \
                unsigned long long ml = m & lmask;                               \
                if (ml) {                                                        \
                    float dx = vx - (float)(63 - __clzll((long long)ml));        \
                    best = fminf(best, fmaf(dx, dx, dy2));                       \
                }                                                                \
                unsigned long long mr = (m >> xc) >> 1;                          \
                if (mr) {                                                        \
                    float dx = (float)(xc + __ffsll((long long)mr)) - vx;        \
                    best = fminf(best, fmaf(dx, dx, dy2));                       \
                }                                                                \
            } } while (0)

            for (int d = 0; d < 64; d++) {
                if (d > 0 && best <= (float)((d - 1) * (d - 1))) break;
                int yd = cy + d;
                if (yd < 64) { float dy = vy - (float)yd; if (dy * dy < best) ROW_EVAL(yd, dy); }
                if (d > 0) {
                    int yu = cy - d;
                    if (yu >= 0) { float dy = vy - (float)yu; if (dy * dy < best) ROW_EVAL(yu, dy); }
                }
            }
            s = (best >= 1.0e17f) ? BIGF : sqrt_ap(best) * INV64;
        }
    }

    // ===== block reduce (shuffle) -> partial; last finisher sums all =====
    {
        float v = s;
#pragma unroll
        for (int o = 16; o > 0; o >>= 1) v += __shfl_down_sync(0xffffffffu, v, o);
        if (lane == 0) red[wid] = v;
    }
    __syncthreads();
    if (tid == 0) {
        float v = 0.f;
#pragma unroll
        for (int w = 0; w < 8; w++) v += red[w];
        g_partial[bx] = v;
        __threadfence();
        unsigned t = atomicAdd(&g_ticket, 1u);
        lastflag = ((t % (unsigned)NBLK) == (unsigned)(NBLK - 1));
    }
    __syncthreads();
    if (lastflag) {
        __threadfence();
        float v = (tid < NBLK) ? *(volatile float*)&g_partial[tid] : 0.0f;
#pragma unroll
        for (int o = 16; o > 0; o >>= 1) v += __shfl_down_sync(0xffffffffu, v, o);
        if (lane == 0) red[wid] = v;
        __syncthreads();
        if (tid == 0) {
            float r = 0.f;
#pragma unroll
            for (int w = 0; w < 8; w++) r += red[w];
            out[0] = r;
        }
    }
}

extern "C" void kernel_launch(void* const* d_in, const int* in_sizes, int n_in,
                              void* d_out, int out_size) {
    const float* vert2d = (const float*)d_in[0];   // [B, N, 2] float32 (pixel units)
    const int*   mask   = (const int*)d_in[1];     // [B, H, W] int32
    float* out = (float*)d_out;
    (void)in_sizes; (void)n_in; (void)out_size;

    static int configured = 0;
    if (!configured) {
        cudaFuncSetAttribute(k_fused, cudaFuncAttributeMaxDynamicSharedMemorySize, SMEM_BYTES);
        configured = 1;
    }
    k_fused<<<NBLK, 256, SMEM_BYTES>>>(vert2d, mask, out);
}